// round 10
// baseline (speedup 1.0000x reference)
#include <cuda_runtime.h>
#include <cuda_fp16.h>
#include <cstdint>
#include <math.h>

// ---------------------------------------------------------------------------
// LegalMultiHeadAttention — Round 10: fp16 m16n8k16 path + ldmatrix fragment
// loads (4x fewer smem-load instructions) + 4-stage cp.async pipeline.
// Fused softmax kept: scores -> exp fp16 + psum; invsum; av normalizes
// (fp32 attn out from smem) + computes HO.
//   B=2, S=4096, D_MODEL=1024, H=4, D_K=256.
// ---------------------------------------------------------------------------

#define SEQ    4096
#define DK     256
#define DM     1024
#define NH     4
#define NB     2
#define BS_TOT (NB*SEQ)          // 8192
#define NROWS  (NH*NB*SEQ)       // 32768

__device__ __half g_qin[(size_t)BS_TOT*DM];
__device__ __half g_kin[(size_t)BS_TOT*DM];
__device__ __half g_vin[(size_t)BS_TOT*DM];
__device__ __half g_Qh [(size_t)NH*BS_TOT*DK];
__device__ __half g_Kh [(size_t)NH*BS_TOT*DK];
__device__ __half g_Vh [(size_t)NH*BS_TOT*DK];
__device__ __half g_VTh[(size_t)NH*BS_TOT*DK];
__device__ __half g_HOh[(size_t)BS_TOT*DM];
__device__ __half g_WTh[(size_t)3*NH*DK*DM];
__device__ __half g_WoTh[(size_t)DM*DM];
__device__ __half g_Eh [(size_t)NH*NB*SEQ*SEQ];   // unnormalized exp
__device__ float  g_psum[(size_t)NROWS*64];
__device__ float  g_invsum[NROWS];
__device__ float  g_attn_fallback[(size_t)NH*NB*SEQ*SEQ];

__device__ __forceinline__ uint32_t smem_u32(const void* p) {
    uint32_t a;
    asm("{ .reg .u64 t; cvta.to.shared.u64 t, %1; cvt.u32.u64 %0, t; }"
        : "=r"(a) : "l"(p));
    return a;
}
__device__ __forceinline__ void mma_f16(float& c0, float& c1, float& c2, float& c3,
                                        uint32_t a0, uint32_t a1, uint32_t a2, uint32_t a3,
                                        uint32_t b0, uint32_t b1) {
    asm volatile(
        "mma.sync.aligned.m16n8k16.row.col.f32.f16.f16.f32 "
        "{%0,%1,%2,%3}, {%4,%5,%6,%7}, {%8,%9}, {%0,%1,%2,%3};"
        : "+f"(c0), "+f"(c1), "+f"(c2), "+f"(c3)
        : "r"(a0), "r"(a1), "r"(a2), "r"(a3), "r"(b0), "r"(b1));
}
__device__ __forceinline__ void ldsm4(uint32_t& r0, uint32_t& r1, uint32_t& r2, uint32_t& r3,
                                      uint32_t addr) {
    asm volatile("ldmatrix.sync.aligned.m8n8.x4.shared.b16 {%0,%1,%2,%3}, [%4];"
                 : "=r"(r0), "=r"(r1), "=r"(r2), "=r"(r3) : "r"(addr));
}
__device__ __forceinline__ void cp16(uint32_t dst, const void* src) {
    asm volatile("cp.async.cg.shared.global [%0], [%1], 16;" :: "r"(dst), "l"(src));
}

#define NSTAGE 4
#define BUF_WORDS 6144                       // 384 rows * 16 words (32 fp16)
#define SMEM_BYTES (NSTAGE*BUF_WORDS*4)      // 98304

// ---------------------------------------------------------------------------
// fp16 GEMM NT: C[m,n] = alpha*sum_k A[m,k]*B[n,k] (+bias[n]).
// 256 threads = 8 warps (WGM x WGN), warp tile 64x64, K staged 32/stage.
// smem: 16 words per row-stage; word kp swizzled by ((row>>1)&3)<<2.
// Fragments via ldmatrix.x4. MODE 0 plain | 1 scores | 2 av.
// ---------------------------------------------------------------------------
template<int WGM, int WGN, bool HASBIAS, bool OUTHALF, int MODE>
__device__ __forceinline__ void gemm_h(const __half* __restrict__ A, int lda,
                                       const __half* __restrict__ B, int ldb,
                                       void* __restrict__ Cv, int ldc,
                                       int K, float alpha, const float* __restrict__ bias,
                                       float* __restrict__ aux,
                                       const float* __restrict__ invrow)
{
    extern __shared__ uint32_t smem[];
    const uint32_t sbase = smem_u32(smem);

    const int tid  = threadIdx.x;           // 256
    const int wid  = tid >> 5;
    const int lane = tid & 31;
    const int grp  = lane >> 2;
    const int tg   = lane & 3;
    const int wm   = (wid / WGN) * 64;
    const int wn   = (wid % WGN) * 64;
    const int lrow = lane & 15;              // ldmatrix row-within-16
    const int lk4  = (lane >> 4) << 2;       // ldmatrix k-half word offset

    const long bm = (long)blockIdx.y * (WGM * 64);
    const long bn = (long)blockIdx.x * (WGN * 64);
    A += bm * (long)lda;
    B += bn * (long)ldb;

    const int sm4 = tid >> 2;                // 0..63
    const int c4  = tid & 3;

    float invs[WGM > 0 ? WGM : 1];
    if (MODE == 2) {
#pragma unroll
        for (int c = 0; c < WGM; c++)
            invs[c] = invrow[bm + sm4 + c * 64];
    }

    float acc[4][8][4];
#pragma unroll
    for (int i = 0; i < 4; i++)
#pragma unroll
        for (int j = 0; j < 8; j++)
#pragma unroll
            for (int r = 0; r < 4; r++) acc[i][j][r] = 0.0f;

    const int NIT = K >> 5;
    const int AWORDS = WGM * 64 * 16;

    auto stage_copy = [&](int stage, int buf) {
        const uint32_t db = sbase + (uint32_t)buf * (BUF_WORDS * 4);
        const __half* Ak = A + stage * 32 + c4 * 8;
        const __half* Bk = B + stage * 32 + c4 * 8;
#pragma unroll
        for (int c = 0; c < WGM; c++) {
            const int r = sm4 + c * 64;
            const int w = r * 16 + ((c4 * 4) ^ (((r >> 1) & 3) << 2));
            cp16(db + (uint32_t)w * 4, Ak + (long)r * lda);
        }
        const uint32_t dbB = db + (uint32_t)AWORDS * 4;
#pragma unroll
        for (int c = 0; c < WGN; c++) {
            const int r = sm4 + c * 64;
            const int w = r * 16 + ((c4 * 4) ^ (((r >> 1) & 3) << 2));
            cp16(dbB + (uint32_t)w * 4, Bk + (long)r * ldb);
        }
        asm volatile("cp.async.commit_group;" ::: "memory");
    };

    stage_copy(0, 0);
    stage_copy(1, 1);
    stage_copy(2, 2);

    int cbuf = 0;
#pragma unroll 1
    for (int it = 0; it < NIT; it++) {
        asm volatile("cp.async.wait_group %0;" :: "n"(NSTAGE - 2) : "memory");
        __syncthreads();
        if (it + 3 < NIT) {
            int nb = cbuf + 3; if (nb >= NSTAGE) nb -= NSTAGE;
            stage_copy(it + 3, nb);
        }

        const uint32_t* sA = smem + cbuf * BUF_WORDS;
        const uint32_t sAaddr = sbase + (uint32_t)cbuf * (BUF_WORDS * 4);
        const uint32_t sBaddr = sAaddr + (uint32_t)AWORDS * 4;

        // MODE 2: write normalized fp32 attn back (each element staged once)
        if (MODE == 2) {
#pragma unroll
            for (int c = 0; c < WGM; c++) {
                const int m = sm4 + c * 64;
                const int w = m * 16 + ((c4 * 4) ^ (((m >> 1) & 3) << 2));
                const uint4 d = *reinterpret_cast<const uint4*>(sA + w);
                const float iv = invs[c];
                float2 f0 = __half22float2(*reinterpret_cast<const __half2*>(&d.x));
                float2 f1 = __half22float2(*reinterpret_cast<const __half2*>(&d.y));
                float2 f2 = __half22float2(*reinterpret_cast<const __half2*>(&d.z));
                float2 f3 = __half22float2(*reinterpret_cast<const __half2*>(&d.w));
                float4 o0 = make_float4(f0.x * iv, f0.y * iv, f1.x * iv, f1.y * iv);
                float4 o1 = make_float4(f2.x * iv, f2.y * iv, f3.x * iv, f3.y * iv);
                float* dst = aux + (bm + m) * (long)lda + it * 32 + c4 * 8;
                *reinterpret_cast<float4*>(dst)     = o0;
                *reinterpret_cast<float4*>(dst + 4) = o1;
            }
        }

#pragma unroll
        for (int ks = 0; ks < 2; ks++) {
            const int kb = ks * 8;
            uint32_t af[4][4];
#pragma unroll
            for (int mt = 0; mt < 4; mt++) {
                const int row = wm + mt * 16 + lrow;
                const int w   = (kb + lk4) ^ (((row >> 1) & 3) << 2);
                ldsm4(af[mt][0], af[mt][1], af[mt][2], af[mt][3],
                      sAaddr + (uint32_t)(row * 16 + w) * 4);
            }
            uint32_t bf[8][2];
#pragma unroll
            for (int p = 0; p < 4; p++) {
                const int row = wn + p * 16 + lrow;
                const int w   = (kb + lk4) ^ (((row >> 1) & 3) << 2);
                ldsm4(bf[2*p][0], bf[2*p+1][0], bf[2*p][1], bf[2*p+1][1],
                      sBaddr + (uint32_t)(row * 16 + w) * 4);
            }
#pragma unroll
            for (int mt = 0; mt < 4; mt++)
#pragma unroll
                for (int nt = 0; nt < 8; nt++)
                    mma_f16(acc[mt][nt][0], acc[mt][nt][1], acc[mt][nt][2], acc[mt][nt][3],
                            af[mt][0], af[mt][1], af[mt][2], af[mt][3],
                            bf[nt][0], bf[nt][1]);
        }
        cbuf++; if (cbuf >= NSTAGE) cbuf = 0;
    }

    // ---- epilogue ----
    if (MODE == 1) {
        __half* Ch = (__half*)Cv;
        const int ct = (int)((bn + wn) >> 6);
#pragma unroll
        for (int mt = 0; mt < 4; mt++) {
            const long r0 = bm + wm + mt * 16 + grp;
            float rs0 = 0.0f, rs1 = 0.0f;
#pragma unroll
            for (int nt = 0; nt < 8; nt++) {
                const int cn = (int)bn + wn + nt * 8 + 2 * tg;
                const float e00 = __expf(acc[mt][nt][0] * alpha);
                const float e01 = __expf(acc[mt][nt][1] * alpha);
                const float e10 = __expf(acc[mt][nt][2] * alpha);
                const float e11 = __expf(acc[mt][nt][3] * alpha);
                const __half2 h0 = __floats2half2_rn(e00, e01);
                const __half2 h1 = __floats2half2_rn(e10, e11);
                const float2 b0 = __half22float2(h0);
                const float2 b1 = __half22float2(h1);
                rs0 += b0.x + b0.y;
                rs1 += b1.x + b1.y;
                *reinterpret_cast<__half2*>(Ch + r0 * (long)ldc + cn)       = h0;
                *reinterpret_cast<__half2*>(Ch + (r0 + 8) * (long)ldc + cn) = h1;
            }
            rs0 += __shfl_xor_sync(0xffffffffu, rs0, 1);
            rs0 += __shfl_xor_sync(0xffffffffu, rs0, 2);
            rs1 += __shfl_xor_sync(0xffffffffu, rs1, 1);
            rs1 += __shfl_xor_sync(0xffffffffu, rs1, 2);
            if (tg == 0) {
                aux[(size_t)r0 * 64 + ct]       = rs0;
                aux[(size_t)(r0 + 8) * 64 + ct] = rs1;
            }
        }
    } else {
#pragma unroll
        for (int mt = 0; mt < 4; mt++) {
            const long r0 = bm + wm + mt * 16 + grp;
            float s0 = 1.0f, s1 = 1.0f;
            if (MODE == 2) { s0 = invrow[r0]; s1 = invrow[r0 + 8]; }
#pragma unroll
            for (int nt = 0; nt < 8; nt++) {
                const int cn = (int)bn + wn + nt * 8 + 2 * tg;
                float v00 = acc[mt][nt][0] * alpha * s0;
                float v01 = acc[mt][nt][1] * alpha * s0;
                float v10 = acc[mt][nt][2] * alpha * s1;
                float v11 = acc[mt][nt][3] * alpha * s1;
                if (HASBIAS) {
                    const float b0 = bias[cn], b1 = bias[cn + 1];
                    v00 += b0; v01 += b1;
                    v10 += b0; v11 += b1;
                }
                if (OUTHALF) {
                    __half* Ch = (__half*)Cv;
                    *reinterpret_cast<__half2*>(Ch + r0 * (long)ldc + cn)       = __floats2half2_rn(v00, v01);
                    *reinterpret_cast<__half2*>(Ch + (r0 + 8) * (long)ldc + cn) = __floats2half2_rn(v10, v11);
                } else {
                    float* Cf = (float*)Cv;
                    *reinterpret_cast<float2*>(Cf + r0 * (long)ldc + cn)       = make_float2(v00, v01);
                    *reinterpret_cast<float2*>(Cf + (r0 + 8) * (long)ldc + cn) = make_float2(v10, v11);
                }
            }
        }
    }
}

// ---------------------------------------------------------------------------
__global__ void __launch_bounds__(256) f2h_kernel(const float* __restrict__ q,
                                                  const float* __restrict__ k,
                                                  const float* __restrict__ v)
{
    const int z = blockIdx.y;
    const float* src = z == 0 ? q : z == 1 ? k : v;
    __half* dst = z == 0 ? g_qin : z == 1 ? g_kin : g_vin;
    const size_t i = (size_t)blockIdx.x * 256 + threadIdx.x;
    const float4 val = reinterpret_cast<const float4*>(src)[i];
    __half2 h0 = __floats2half2_rn(val.x, val.y);
    __half2 h1 = __floats2half2_rn(val.z, val.w);
    uint2 o;
    o.x = *reinterpret_cast<uint32_t*>(&h0);
    o.y = *reinterpret_cast<uint32_t*>(&h1);
    reinterpret_cast<uint2*>(dst)[i] = o;
}

__global__ void __launch_bounds__(256) transw_kernel(const float* __restrict__ in,
                                                     int which, int R, int C)
{
    __shared__ float t[32][33];
    const int z = blockIdx.z;
    const float* src;
    __half* dst;
    if (which == 3) { src = in; dst = g_WoTh; }
    else            { src = in + (size_t)z * R * C; dst = g_WTh + ((size_t)which * NH + z) * R * C; }

    const int c0 = blockIdx.x * 32, r0 = blockIdx.y * 32;
    const int tx = threadIdx.x & 31, ty = threadIdx.x >> 5;
#pragma unroll
    for (int i = 0; i < 4; i++)
        t[ty + i * 8][tx] = src[(size_t)(r0 + ty + i * 8) * C + c0 + tx];
    __syncthreads();
#pragma unroll
    for (int i = 0; i < 4; i++)
        dst[(size_t)(c0 + ty + i * 8) * R + r0 + tx] = __float2half_rn(t[tx][ty + i * 8]);
}

__global__ void __launch_bounds__(256) transv_kernel()
{
    __shared__ __half t[32][34];
    const int z = blockIdx.z;
    const __half* src = g_Vh + (size_t)z * SEQ * DK;
    __half* dst = g_VTh + (size_t)z * SEQ * DK;
    const int c0 = blockIdx.x * 32, r0 = blockIdx.y * 32;
    const int tx = threadIdx.x & 31, ty = threadIdx.x >> 5;
#pragma unroll
    for (int i = 0; i < 4; i++)
        t[ty + i * 8][tx] = src[(size_t)(r0 + ty + i * 8) * DK + c0 + tx];
    __syncthreads();
#pragma unroll
    for (int i = 0; i < 4; i++)
        dst[(size_t)(c0 + ty + i * 8) * SEQ + r0 + tx] = t[tx][ty + i * 8];
}

__global__ void __launch_bounds__(256) invsum_kernel()
{
    const int row  = blockIdx.x * 8 + (threadIdx.x >> 5);
    const int lane = threadIdx.x & 31;
    float s = g_psum[(size_t)row * 64 + lane] + g_psum[(size_t)row * 64 + 32 + lane];
#pragma unroll
    for (int o = 16; o > 0; o >>= 1) s += __shfl_xor_sync(0xffffffffu, s, o);
    if (lane == 0) g_invsum[row] = 1.0f / s;
}

// ---------------------------------------------------------------------------
__global__ void __launch_bounds__(256, 1) proj_tc(
    const float* __restrict__ bq, const float* __restrict__ bk, const float* __restrict__ bv)
{
    const int z = blockIdx.z, mat = z >> 2, head = z & 3;
    const __half* A    = mat == 0 ? g_qin : mat == 1 ? g_kin : g_vin;
    const __half* B    = g_WTh + (size_t)z * DK * DM;
    const float*  bias = (mat == 0 ? bq : mat == 1 ? bk : bv) + head * DK;
    __half* C = (mat == 0 ? g_Qh : mat == 1 ? g_Kh : g_Vh) + (size_t)head * BS_TOT * DK;
    gemm_h<2, 4, true, true, 0>(A, DM, B, DM, C, DK, DM, 1.0f, bias, nullptr, nullptr);
}

__global__ void __launch_bounds__(256, 1) scores_tc()
{
    const int z = blockIdx.z;
    gemm_h<4, 2, false, true, 1>(g_Qh + (size_t)z * SEQ * DK, DK,
                                 g_Kh + (size_t)z * SEQ * DK, DK,
                                 g_Eh + (size_t)z * SEQ * SEQ, SEQ, DK, 0.0625f,
                                 nullptr, g_psum + (size_t)z * SEQ * 64, nullptr);
}

__global__ void __launch_bounds__(256, 1) av_tc(float* __restrict__ attn_out)
{
    float* attn = attn_out ? attn_out : g_attn_fallback;
    const int z = blockIdx.z, h = z >> 1, b = z & 1;
    gemm_h<2, 4, false, true, 2>(g_Eh + (size_t)z * SEQ * SEQ, SEQ,
                                 g_VTh + (size_t)z * DK * SEQ, SEQ,
                                 g_HOh + (size_t)b * SEQ * DM + h * DK, DM, SEQ, 1.0f,
                                 nullptr,
                                 attn + (size_t)z * SEQ * SEQ,
                                 g_invsum + (size_t)z * SEQ);
}

__global__ void __launch_bounds__(256, 1) outproj_tc(const float* __restrict__ bo,
                                                     float* __restrict__ out)
{
    gemm_h<2, 4, true, false, 0>(g_HOh, DM, g_WoTh, DM, out, DM, DM, 1.0f, bo,
                                 nullptr, nullptr);
}

// ---------------------------------------------------------------------------
extern "C" void kernel_launch(void* const* d_in, const int* in_sizes, int n_in,
                              void* d_out, int out_size)
{
    const float* q  = (const float*)d_in[0];
    const float* k  = (const float*)d_in[1];
    const float* v  = (const float*)d_in[2];
    const float* Wq = (const float*)d_in[3];
    const float* bq = (const float*)d_in[4];
    const float* Wk = (const float*)d_in[5];
    const float* bk = (const float*)d_in[6];
    const float* Wv = (const float*)d_in[7];
    const float* bv = (const float*)d_in[8];
    const float* Wo = (const float*)d_in[9];
    const float* bo = (const float*)d_in[10];

    float* out = (float*)d_out;
    const long OUT_ELEMS  = (long)NB * SEQ * DM;
    const long ATTN_ELEMS = (long)NH * NB * SEQ * SEQ;
    float* attn_out = nullptr;
    if ((long)out_size >= OUT_ELEMS + ATTN_ELEMS) attn_out = out + OUT_ELEMS;

    cudaFuncSetAttribute(proj_tc,    cudaFuncAttributeMaxDynamicSharedMemorySize, SMEM_BYTES);
    cudaFuncSetAttribute(scores_tc,  cudaFuncAttributeMaxDynamicSharedMemorySize, SMEM_BYTES);
    cudaFuncSetAttribute(av_tc,      cudaFuncAttributeMaxDynamicSharedMemorySize, SMEM_BYTES);
    cudaFuncSetAttribute(outproj_tc, cudaFuncAttributeMaxDynamicSharedMemorySize, SMEM_BYTES);

    f2h_kernel<<<dim3(BS_TOT * DM / 4 / 256, 3), 256>>>(q, k, v);

    transw_kernel<<<dim3(8, 32, 4),  256>>>(Wq, 0, DM, DK);
    transw_kernel<<<dim3(8, 32, 4),  256>>>(Wk, 1, DM, DK);
    transw_kernel<<<dim3(8, 32, 4),  256>>>(Wv, 2, DM, DK);
    transw_kernel<<<dim3(32, 32, 1), 256>>>(Wo, 3, DM, DM);

    proj_tc<<<dim3(1, 64, 12), 256, SMEM_BYTES>>>(bq, bk, bv);

    transv_kernel<<<dim3(8, 128, 8), 256>>>();

    scores_tc<<<dim3(32, 16, 8), 256, SMEM_BYTES>>>();

    invsum_kernel<<<dim3(NROWS / 8), 256>>>();

    av_tc<<<dim3(1, 32, 8), 256, SMEM_BYTES>>>(attn_out);

    outproj_tc<<<dim3(4, 64, 1), 256, SMEM_BYTES>>>(bo, out);
}

// round 11
// speedup vs baseline: 1.0203x; 1.0203x over previous
#include <cuda_runtime.h>
#include <cuda_fp16.h>
#include <cstdint>
#include <math.h>

// ---------------------------------------------------------------------------
// LegalMultiHeadAttention — Round 11: R9 datapath (fp16 m16n8k16, LDS frags,
// 3-stage cp.async) + V^T fused into proj epilogue (transv kernel removed)
// + single merged weight-transpose launch.
//   B=2, S=4096, D_MODEL=1024, H=4, D_K=256.
// ---------------------------------------------------------------------------

#define SEQ    4096
#define DK     256
#define DM     1024
#define NH     4
#define NB     2
#define BS_TOT (NB*SEQ)          // 8192
#define NROWS  (NH*NB*SEQ)       // 32768

__device__ __half g_qin[(size_t)BS_TOT*DM];
__device__ __half g_kin[(size_t)BS_TOT*DM];
__device__ __half g_vin[(size_t)BS_TOT*DM];
__device__ __half g_Qh [(size_t)NH*BS_TOT*DK];
__device__ __half g_Kh [(size_t)NH*BS_TOT*DK];
__device__ __half g_VTh[(size_t)NH*BS_TOT*DK];    // [z][DK][SEQ], written by proj
__device__ __half g_HOh[(size_t)BS_TOT*DM];
__device__ __half g_WTh[(size_t)3*NH*DK*DM];
__device__ __half g_WoTh[(size_t)DM*DM];
__device__ __half g_Eh [(size_t)NH*NB*SEQ*SEQ];   // unnormalized exp
__device__ float  g_psum[(size_t)NROWS*64];
__device__ float  g_invsum[NROWS];
__device__ float  g_attn_fallback[(size_t)NH*NB*SEQ*SEQ];

__device__ __forceinline__ uint32_t smem_u32(const void* p) {
    uint32_t a;
    asm("{ .reg .u64 t; cvta.to.shared.u64 t, %1; cvt.u32.u64 %0, t; }"
        : "=r"(a) : "l"(p));
    return a;
}
__device__ __forceinline__ void mma_f16(float& c0, float& c1, float& c2, float& c3,
                                        uint32_t a0, uint32_t a1, uint32_t a2, uint32_t a3,
                                        uint32_t b0, uint32_t b1) {
    asm volatile(
        "mma.sync.aligned.m16n8k16.row.col.f32.f16.f16.f32 "
        "{%0,%1,%2,%3}, {%4,%5,%6,%7}, {%8,%9}, {%0,%1,%2,%3};"
        : "+f"(c0), "+f"(c1), "+f"(c2), "+f"(c3)
        : "r"(a0), "r"(a1), "r"(a2), "r"(a3), "r"(b0), "r"(b1));
}
__device__ __forceinline__ void cp16(uint32_t dst, const void* src) {
    asm volatile("cp.async.cg.shared.global [%0], [%1], 16;" :: "r"(dst), "l"(src));
}

#define NSTAGE 3
#define BUF_WORDS 6144                       // 384 rows * 16 words (32 fp16)
#define SMEM_BYTES (NSTAGE*BUF_WORDS*4)      // 73728

// ---------------------------------------------------------------------------
// fp16 GEMM NT: C[m,n] = alpha*sum_k A[m,k]*B[n,k] (+bias[n]).
// 256 threads = 8 warps (WGM x WGN), warp tile 64x64, K staged 32/stage.
// smem: 16 uint32 words per row-stage; word kp swizzled by ((row>>1)&3)<<2.
// MODE 0 plain | 1 scores (exp+psum) | 2 av (attn writeback + invrow scale)
//      | 3 transposed store: C[n][m] (ldc = M-stride), for V^T.
// ---------------------------------------------------------------------------
template<int WGM, int WGN, bool HASBIAS, bool OUTHALF, int MODE>
__device__ __forceinline__ void gemm_h(const __half* __restrict__ A, int lda,
                                       const __half* __restrict__ B, int ldb,
                                       void* __restrict__ Cv, int ldc,
                                       int K, float alpha, const float* __restrict__ bias,
                                       float* __restrict__ aux,
                                       const float* __restrict__ invrow)
{
    extern __shared__ uint32_t smem[];
    const uint32_t sbase = smem_u32(smem);

    const int tid  = threadIdx.x;           // 256
    const int wid  = tid >> 5;
    const int lane = tid & 31;
    const int grp  = lane >> 2;
    const int tg   = lane & 3;
    const int wm   = (wid / WGN) * 64;
    const int wn   = (wid % WGN) * 64;

    const long bm = (long)blockIdx.y * (WGM * 64);
    const long bn = (long)blockIdx.x * (WGN * 64);
    A += bm * (long)lda;
    B += bn * (long)ldb;

    const int sm4 = tid >> 2;                // 0..63
    const int c4  = tid & 3;

    float invs[WGM > 0 ? WGM : 1];
    if (MODE == 2) {
#pragma unroll
        for (int c = 0; c < WGM; c++)
            invs[c] = invrow[bm + sm4 + c * 64];
    }

    float acc[4][8][4];
#pragma unroll
    for (int i = 0; i < 4; i++)
#pragma unroll
        for (int j = 0; j < 8; j++)
#pragma unroll
            for (int r = 0; r < 4; r++) acc[i][j][r] = 0.0f;

    const int NIT = K >> 5;
    const int AWORDS = WGM * 64 * 16;

    auto stage_copy = [&](int stage, int buf) {
        const uint32_t db = sbase + (uint32_t)buf * (BUF_WORDS * 4);
        const __half* Ak = A + stage * 32 + c4 * 8;
        const __half* Bk = B + stage * 32 + c4 * 8;
#pragma unroll
        for (int c = 0; c < WGM; c++) {
            const int r = sm4 + c * 64;
            const int w = r * 16 + ((c4 * 4) ^ (((r >> 1) & 3) << 2));
            cp16(db + (uint32_t)w * 4, Ak + (long)r * lda);
        }
        const uint32_t dbB = db + (uint32_t)AWORDS * 4;
#pragma unroll
        for (int c = 0; c < WGN; c++) {
            const int r = sm4 + c * 64;
            const int w = r * 16 + ((c4 * 4) ^ (((r >> 1) & 3) << 2));
            cp16(dbB + (uint32_t)w * 4, Bk + (long)r * ldb);
        }
        asm volatile("cp.async.commit_group;" ::: "memory");
    };

    stage_copy(0, 0);
    stage_copy(1, 1);

    int cbuf = 0;
#pragma unroll 1
    for (int it = 0; it < NIT; it++) {
        asm volatile("cp.async.wait_group %0;" :: "n"(NSTAGE - 2) : "memory");
        __syncthreads();
        if (it + 2 < NIT) {
            int nb = cbuf + 2; if (nb >= NSTAGE) nb -= NSTAGE;
            stage_copy(it + 2, nb);
        }

        const uint32_t* sA = smem + cbuf * BUF_WORDS;
        const uint32_t* sB = sA + AWORDS;

        // MODE 2: write normalized fp32 attn back (each element staged once)
        if (MODE == 2) {
#pragma unroll
            for (int c = 0; c < WGM; c++) {
                const int m = sm4 + c * 64;
                const int w = m * 16 + ((c4 * 4) ^ (((m >> 1) & 3) << 2));
                const uint4 d = *reinterpret_cast<const uint4*>(sA + w);
                const float iv = invs[c];
                float2 f0 = __half22float2(*reinterpret_cast<const __half2*>(&d.x));
                float2 f1 = __half22float2(*reinterpret_cast<const __half2*>(&d.y));
                float2 f2 = __half22float2(*reinterpret_cast<const __half2*>(&d.z));
                float2 f3 = __half22float2(*reinterpret_cast<const __half2*>(&d.w));
                float4 o0 = make_float4(f0.x * iv, f0.y * iv, f1.x * iv, f1.y * iv);
                float4 o1 = make_float4(f2.x * iv, f2.y * iv, f3.x * iv, f3.y * iv);
                float* dst = aux + (bm + m) * (long)lda + it * 32 + c4 * 8;
                *reinterpret_cast<float4*>(dst)     = o0;
                *reinterpret_cast<float4*>(dst + 4) = o1;
            }
        }

#pragma unroll
        for (int ks = 0; ks < 2; ks++) {
            const int kb = ks * 8;
            uint32_t af[4][4];
#pragma unroll
            for (int mt = 0; mt < 4; mt++) {
                const int r0 = wm + mt * 16 + grp;
                const int r1 = r0 + 8;
                const int s0 = ((r0 >> 1) & 3) << 2;
                const int s1 = ((r1 >> 1) & 3) << 2;
                af[mt][0] = sA[r0 * 16 + ((kb + tg)     ^ s0)];
                af[mt][1] = sA[r1 * 16 + ((kb + tg)     ^ s1)];
                af[mt][2] = sA[r0 * 16 + ((kb + tg + 4) ^ s0)];
                af[mt][3] = sA[r1 * 16 + ((kb + tg + 4) ^ s1)];
            }
            uint32_t bf[8][2];
#pragma unroll
            for (int nt = 0; nt < 8; nt++) {
                const int rb = wn + nt * 8 + grp;
                const int sb = ((rb >> 1) & 3) << 2;
                bf[nt][0] = sB[rb * 16 + ((kb + tg)     ^ sb)];
                bf[nt][1] = sB[rb * 16 + ((kb + tg + 4) ^ sb)];
            }
#pragma unroll
            for (int mt = 0; mt < 4; mt++)
#pragma unroll
                for (int nt = 0; nt < 8; nt++)
                    mma_f16(acc[mt][nt][0], acc[mt][nt][1], acc[mt][nt][2], acc[mt][nt][3],
                            af[mt][0], af[mt][1], af[mt][2], af[mt][3],
                            bf[nt][0], bf[nt][1]);
        }
        cbuf++; if (cbuf >= NSTAGE) cbuf = 0;
    }

    // ---- epilogue ----
    if (MODE == 1) {
        __half* Ch = (__half*)Cv;
        const int ct = (int)((bn + wn) >> 6);
#pragma unroll
        for (int mt = 0; mt < 4; mt++) {
            const long r0 = bm + wm + mt * 16 + grp;
            float rs0 = 0.0f, rs1 = 0.0f;
#pragma unroll
            for (int nt = 0; nt < 8; nt++) {
                const int cn = (int)bn + wn + nt * 8 + 2 * tg;
                const float e00 = __expf(acc[mt][nt][0] * alpha);
                const float e01 = __expf(acc[mt][nt][1] * alpha);
                const float e10 = __expf(acc[mt][nt][2] * alpha);
                const float e11 = __expf(acc[mt][nt][3] * alpha);
                const __half2 h0 = __floats2half2_rn(e00, e01);
                const __half2 h1 = __floats2half2_rn(e10, e11);
                const float2 b0 = __half22float2(h0);
                const float2 b1 = __half22float2(h1);
                rs0 += b0.x + b0.y;
                rs1 += b1.x + b1.y;
                *reinterpret_cast<__half2*>(Ch + r0 * (long)ldc + cn)       = h0;
                *reinterpret_cast<__half2*>(Ch + (r0 + 8) * (long)ldc + cn) = h1;
            }
            rs0 += __shfl_xor_sync(0xffffffffu, rs0, 1);
            rs0 += __shfl_xor_sync(0xffffffffu, rs0, 2);
            rs1 += __shfl_xor_sync(0xffffffffu, rs1, 1);
            rs1 += __shfl_xor_sync(0xffffffffu, rs1, 2);
            if (tg == 0) {
                aux[(size_t)r0 * 64 + ct]       = rs0;
                aux[(size_t)(r0 + 8) * 64 + ct] = rs1;
            }
        }
    } else if (MODE == 3) {
        // transposed fp16 store: C[n][m], ldc = M-stride (SEQ).
        __half* Ch = (__half*)Cv;
#pragma unroll
        for (int mt = 0; mt < 4; mt++) {
            const long r0 = bm + wm + mt * 16 + grp;   // m index
#pragma unroll
            for (int nt = 0; nt < 8; nt++) {
                const int cn = (int)bn + wn + nt * 8 + 2 * tg;   // n index
                float v00 = acc[mt][nt][0] * alpha;
                float v01 = acc[mt][nt][1] * alpha;
                float v10 = acc[mt][nt][2] * alpha;
                float v11 = acc[mt][nt][3] * alpha;
                if (HASBIAS) {
                    const float b0 = bias[cn], b1 = bias[cn + 1];
                    v00 += b0; v01 += b1;
                    v10 += b0; v11 += b1;
                }
                Ch[(size_t)cn * ldc + r0]           = __float2half_rn(v00);
                Ch[(size_t)(cn + 1) * ldc + r0]     = __float2half_rn(v01);
                Ch[(size_t)cn * ldc + r0 + 8]       = __float2half_rn(v10);
                Ch[(size_t)(cn + 1) * ldc + r0 + 8] = __float2half_rn(v11);
            }
        }
    } else {
#pragma unroll
        for (int mt = 0; mt < 4; mt++) {
            const long r0 = bm + wm + mt * 16 + grp;
            float s0 = 1.0f, s1 = 1.0f;
            if (MODE == 2) { s0 = invrow[r0]; s1 = invrow[r0 + 8]; }
#pragma unroll
            for (int nt = 0; nt < 8; nt++) {
                const int cn = (int)bn + wn + nt * 8 + 2 * tg;
                float v00 = acc[mt][nt][0] * alpha * s0;
                float v01 = acc[mt][nt][1] * alpha * s0;
                float v10 = acc[mt][nt][2] * alpha * s1;
                float v11 = acc[mt][nt][3] * alpha * s1;
                if (HASBIAS) {
                    const float b0 = bias[cn], b1 = bias[cn + 1];
                    v00 += b0; v01 += b1;
                    v10 += b0; v11 += b1;
                }
                if (OUTHALF) {
                    __half* Ch = (__half*)Cv;
                    *reinterpret_cast<__half2*>(Ch + r0 * (long)ldc + cn)       = __floats2half2_rn(v00, v01);
                    *reinterpret_cast<__half2*>(Ch + (r0 + 8) * (long)ldc + cn) = __floats2half2_rn(v10, v11);
                } else {
                    float* Cf = (float*)Cv;
                    *reinterpret_cast<float2*>(Cf + r0 * (long)ldc + cn)       = make_float2(v00, v01);
                    *reinterpret_cast<float2*>(Cf + (r0 + 8) * (long)ldc + cn) = make_float2(v10, v11);
                }
            }
        }
    }
}

// ---------------------------------------------------------------------------
__global__ void __launch_bounds__(256) f2h_kernel(const float* __restrict__ q,
                                                  const float* __restrict__ k,
                                                  const float* __restrict__ v)
{
    const int z = blockIdx.y;
    const float* src = z == 0 ? q : z == 1 ? k : v;
    __half* dst = z == 0 ? g_qin : z == 1 ? g_kin : g_vin;
    const size_t i = (size_t)blockIdx.x * 256 + threadIdx.x;
    const float4 val = reinterpret_cast<const float4*>(src)[i];
    __half2 h0 = __floats2half2_rn(val.x, val.y);
    __half2 h1 = __floats2half2_rn(val.z, val.w);
    uint2 o;
    o.x = *reinterpret_cast<uint32_t*>(&h0);
    o.y = *reinterpret_cast<uint32_t*>(&h1);
    reinterpret_cast<uint2*>(dst)[i] = o;
}

// merged weight transpose: z = 0..11 -> Wq/Wk/Wv head slices (8 x-blocks),
// z = 12 -> Wo (32 x-blocks; x >= 8 only used here).
__global__ void __launch_bounds__(256) transw_kernel(
    const float* __restrict__ Wq, const float* __restrict__ Wk,
    const float* __restrict__ Wv, const float* __restrict__ Wo)
{
    __shared__ float t[32][33];
    const int z = blockIdx.z;
    const float* src;
    __half* dst;
    int R, C;
    if (z == 12) { src = Wo; dst = g_WoTh; R = DM; C = DM; }
    else {
        const int mat = z >> 2, head = z & 3;
        const float* W = mat == 0 ? Wq : mat == 1 ? Wk : Wv;
        src = W + (size_t)head * DM * DK;
        dst = g_WTh + (size_t)z * DK * DM;
        R = DM; C = DK;
        if (blockIdx.x >= 8) return;
    }

    const int c0 = blockIdx.x * 32, r0 = blockIdx.y * 32;
    const int tx = threadIdx.x & 31, ty = threadIdx.x >> 5;
#pragma unroll
    for (int i = 0; i < 4; i++)
        t[ty + i * 8][tx] = src[(size_t)(r0 + ty + i * 8) * C + c0 + tx];
    __syncthreads();
#pragma unroll
    for (int i = 0; i < 4; i++)
        dst[(size_t)(c0 + ty + i * 8) * R + r0 + tx] = __float2half_rn(t[tx][ty + i * 8]);
}

__global__ void __launch_bounds__(256) invsum_kernel()
{
    const int row  = blockIdx.x * 8 + (threadIdx.x >> 5);
    const int lane = threadIdx.x & 31;
    float s = g_psum[(size_t)row * 64 + lane] + g_psum[(size_t)row * 64 + 32 + lane];
#pragma unroll
    for (int o = 16; o > 0; o >>= 1) s += __shfl_xor_sync(0xffffffffu, s, o);
    if (lane == 0) g_invsum[row] = 1.0f / s;
}

// ---------------------------------------------------------------------------
// proj: z 0..3 Q heads, 4..7 K heads, 8..11 V heads (V written transposed)
// ---------------------------------------------------------------------------
__global__ void __launch_bounds__(256, 1) proj_tc(
    const float* __restrict__ bq, const float* __restrict__ bk, const float* __restrict__ bv)
{
    const int z = blockIdx.z, mat = z >> 2, head = z & 3;
    const __half* A    = mat == 0 ? g_qin : mat == 1 ? g_kin : g_vin;
    const __half* B    = g_WTh + (size_t)z * DK * DM;
    const float*  bias = (mat == 0 ? bq : mat == 1 ? bk : bv) + head * DK;
    if (mat == 2) {
        // V: write transposed into g_VTh[z'][DK][SEQ], z' = head*NB + b.
        // blockIdx.y covers 64 M-tiles over [B*S]; b = y / 32.
        __half* C = g_VTh + (size_t)head * BS_TOT * DK;   // [head][b][DK][SEQ] contiguous
        // m index within (b,s): rows bm.. map to b = bm/SEQ, s = bm%SEQ.
        // store target: g_VTh[head*NB*SEQ*DK + b*SEQ*DK + n*SEQ + s]
        // Handled via MODE 3 with per-CTA base: C + b*SEQ*DK, ldc=SEQ, and
        // A offset already includes bm; MODE3 uses absolute r0=bm+... so pass
        // C adjusted: subtract b*SEQ from row by giving C - b*SEQ + b*SEQ*DK.
        const long b = (long)blockIdx.y / 32;             // 64 y-tiles, 32 per batch
        __half* Cb = C + b * SEQ * DK - b * SEQ;          // so cn*SEQ + r0 lands right
        gemm_h<2, 4, true, true, 3>(A, DM, B, DM, Cb, SEQ, DM, 1.0f, bias, nullptr, nullptr);
    } else {
        __half* C = (mat == 0 ? g_Qh : g_Kh) + (size_t)head * BS_TOT * DK;
        gemm_h<2, 4, true, true, 0>(A, DM, B, DM, C, DK, DM, 1.0f, bias, nullptr, nullptr);
    }
}

__global__ void __launch_bounds__(256, 1) scores_tc()
{
    const int z = blockIdx.z;
    gemm_h<4, 2, false, true, 1>(g_Qh + (size_t)z * SEQ * DK, DK,
                                 g_Kh + (size_t)z * SEQ * DK, DK,
                                 g_Eh + (size_t)z * SEQ * SEQ, SEQ, DK, 0.0625f,
                                 nullptr, g_psum + (size_t)z * SEQ * 64, nullptr);
}

__global__ void __launch_bounds__(256, 1) av_tc(float* __restrict__ attn_out)
{
    float* attn = attn_out ? attn_out : g_attn_fallback;
    const int z = blockIdx.z, h = z >> 1, b = z & 1;
    gemm_h<2, 4, false, true, 2>(g_Eh + (size_t)z * SEQ * SEQ, SEQ,
                                 g_VTh + (size_t)z * DK * SEQ, SEQ,
                                 g_HOh + (size_t)b * SEQ * DM + h * DK, DM, SEQ, 1.0f,
                                 nullptr,
                                 attn + (size_t)z * SEQ * SEQ,
                                 g_invsum + (size_t)z * SEQ);
}

__global__ void __launch_bounds__(256, 1) outproj_tc(const float* __restrict__ bo,
                                                     float* __restrict__ out)
{
    gemm_h<2, 4, true, false, 0>(g_HOh, DM, g_WoTh, DM, out, DM, DM, 1.0f, bo,
                                 nullptr, nullptr);
}

// ---------------------------------------------------------------------------
extern "C" void kernel_launch(void* const* d_in, const int* in_sizes, int n_in,
                              void* d_out, int out_size)
{
    const float* q  = (const float*)d_in[0];
    const float* k  = (const float*)d_in[1];
    const float* v  = (const float*)d_in[2];
    const float* Wq = (const float*)d_in[3];
    const float* bq = (const float*)d_in[4];
    const float* Wk = (const float*)d_in[5];
    const float* bk = (const float*)d_in[6];
    const float* Wv = (const float*)d_in[7];
    const float* bv = (const float*)d_in[8];
    const float* Wo = (const float*)d_in[9];
    const float* bo = (const float*)d_in[10];

    float* out = (float*)d_out;
    const long OUT_ELEMS  = (long)NB * SEQ * DM;
    const long ATTN_ELEMS = (long)NH * NB * SEQ * SEQ;
    float* attn_out = nullptr;
    if ((long)out_size >= OUT_ELEMS + ATTN_ELEMS) attn_out = out + OUT_ELEMS;

    cudaFuncSetAttribute(proj_tc,    cudaFuncAttributeMaxDynamicSharedMemorySize, SMEM_BYTES);
    cudaFuncSetAttribute(scores_tc,  cudaFuncAttributeMaxDynamicSharedMemorySize, SMEM_BYTES);
    cudaFuncSetAttribute(av_tc,      cudaFuncAttributeMaxDynamicSharedMemorySize, SMEM_BYTES);
    cudaFuncSetAttribute(outproj_tc, cudaFuncAttributeMaxDynamicSharedMemorySize, SMEM_BYTES);

    f2h_kernel<<<dim3(BS_TOT * DM / 4 / 256, 3), 256>>>(q, k, v);

    transw_kernel<<<dim3(32, 32, 13), 256>>>(Wq, Wk, Wv, Wo);

    // proj (Q, K normal; V transposed directly into g_VTh)
    proj_tc<<<dim3(1, 64, 12), 256, SMEM_BYTES>>>(bq, bk, bv);

    // scores: exp(QK^T/16) fp16 + row partial sums
    scores_tc<<<dim3(32, 16, 8), 256, SMEM_BYTES>>>();

    invsum_kernel<<<dim3(NROWS / 8), 256>>>();

    // av: normalized attn (fp32 to d_out) + HO
    av_tc<<<dim3(1, 32, 8), 256, SMEM_BYTES>>>(attn_out);

    outproj_tc<<<dim3(4, 64, 1), 256, SMEM_BYTES>>>(bo, out);
}

// round 12
// speedup vs baseline: 1.1526x; 1.1296x over previous
#include <cuda_runtime.h>
#include <cuda_fp16.h>
#include <cstdint>
#include <math.h>

// ---------------------------------------------------------------------------
// LegalMultiHeadAttention — Round 12: 64-K stages (half the barriers),
// explicit fragment double-buffering across k16 steps, chunk-XOR swizzle.
// fp16 m16n8k16 path, 3-stage cp.async, fused softmax (R8/R11 scheme).
//   B=2, S=4096, D_MODEL=1024, H=4, D_K=256.
// ---------------------------------------------------------------------------

#define SEQ    4096
#define DK     256
#define DM     1024
#define NH     4
#define NB     2
#define BS_TOT (NB*SEQ)          // 8192
#define NROWS  (NH*NB*SEQ)       // 32768

__device__ __half g_qin[(size_t)BS_TOT*DM];
__device__ __half g_kin[(size_t)BS_TOT*DM];
__device__ __half g_vin[(size_t)BS_TOT*DM];
__device__ __half g_Qh [(size_t)NH*BS_TOT*DK];
__device__ __half g_Kh [(size_t)NH*BS_TOT*DK];
__device__ __half g_VTh[(size_t)NH*BS_TOT*DK];    // [z][DK][SEQ], written by proj
__device__ __half g_HOh[(size_t)BS_TOT*DM];
__device__ __half g_WTh[(size_t)3*NH*DK*DM];
__device__ __half g_WoTh[(size_t)DM*DM];
__device__ __half g_Eh [(size_t)NH*NB*SEQ*SEQ];   // unnormalized exp
__device__ float  g_psum[(size_t)NROWS*64];
__device__ float  g_invsum[NROWS];
__device__ float  g_attn_fallback[(size_t)NH*NB*SEQ*SEQ];

__device__ __forceinline__ uint32_t smem_u32(const void* p) {
    uint32_t a;
    asm("{ .reg .u64 t; cvta.to.shared.u64 t, %1; cvt.u32.u64 %0, t; }"
        : "=r"(a) : "l"(p));
    return a;
}
__device__ __forceinline__ void mma_f16(float& c0, float& c1, float& c2, float& c3,
                                        uint32_t a0, uint32_t a1, uint32_t a2, uint32_t a3,
                                        uint32_t b0, uint32_t b1) {
    asm volatile(
        "mma.sync.aligned.m16n8k16.row.col.f32.f16.f16.f32 "
        "{%0,%1,%2,%3}, {%4,%5,%6,%7}, {%8,%9}, {%0,%1,%2,%3};"
        : "+f"(c0), "+f"(c1), "+f"(c2), "+f"(c3)
        : "r"(a0), "r"(a1), "r"(a2), "r"(a3), "r"(b0), "r"(b1));
}
__device__ __forceinline__ void cp16(uint32_t dst, const void* src) {
    asm volatile("cp.async.cg.shared.global [%0], [%1], 16;" :: "r"(dst), "l"(src));
}

#define NSTAGE 3
#define BUF_WORDS 12288                      // 384 rows * 32 words (64 fp16)
#define SMEM_BYTES (NSTAGE*BUF_WORDS*4)      // 147456

// ---------------------------------------------------------------------------
// fp16 GEMM NT: C[m,n] = alpha*sum_k A[m,k]*B[n,k] (+bias[n]).
// 256 threads = 8 warps (WGM x WGN), warp tile 64x64, K staged 64/stage.
// smem row = 32 words (64 halves); 16B chunk c stored at c ^ (row&7).
// MODE 0 plain | 1 scores (exp+psum) | 2 av (attn writeback + invrow scale)
//      | 3 transposed fp16 store C[n][m] (ldc = M-stride) for V^T.
// K must be a multiple of 64.
// ---------------------------------------------------------------------------
template<int WGM, int WGN, bool HASBIAS, bool OUTHALF, int MODE>
__device__ __forceinline__ void gemm_h(const __half* __restrict__ A, int lda,
                                       const __half* __restrict__ B, int ldb,
                                       void* __restrict__ Cv, int ldc,
                                       int K, float alpha, const float* __restrict__ bias,
                                       float* __restrict__ aux,
                                       const float* __restrict__ invrow)
{
    extern __shared__ uint32_t smem[];
    const uint32_t sbase = smem_u32(smem);

    const int tid  = threadIdx.x;           // 256
    const int wid  = tid >> 5;
    const int lane = tid & 31;
    const int grp  = lane >> 2;
    const int tg   = lane & 3;
    const int wm   = (wid / WGN) * 64;
    const int wn   = (wid % WGN) * 64;

    const long bm = (long)blockIdx.y * (WGM * 64);
    const long bn = (long)blockIdx.x * (WGN * 64);
    A += bm * (long)lda;
    B += bn * (long)ldb;

    const int sm8 = tid >> 3;                // 0..31 (row within 32-row pass)
    const int skc = tid & 7;                 // 16B chunk 0..7
    const int w4  = (skc ^ (sm8 & 7)) * 4;   // swizzled chunk word offset

    float invs[2 * WGM];
    if (MODE == 2) {
#pragma unroll
        for (int c = 0; c < 2 * WGM; c++)
            invs[c] = invrow[bm + sm8 + c * 32];
    }

    float acc[4][8][4];
#pragma unroll
    for (int i = 0; i < 4; i++)
#pragma unroll
        for (int j = 0; j < 8; j++)
#pragma unroll
            for (int r = 0; r < 4; r++) acc[i][j][r] = 0.0f;

    const int NIT = K >> 6;
    const int AWORDS = WGM * 64 * 32;

    auto stage_copy = [&](int stage, int buf) {
        const uint32_t db = sbase + (uint32_t)buf * (BUF_WORDS * 4);
        const __half* Ak = A + stage * 64 + skc * 8;
        const __half* Bk = B + stage * 64 + skc * 8;
#pragma unroll
        for (int c = 0; c < 2 * WGM; c++) {
            const int r = sm8 + c * 32;
            cp16(db + (uint32_t)(r * 32 + w4) * 4, Ak + (long)r * lda);
        }
        const uint32_t dbB = db + (uint32_t)AWORDS * 4;
#pragma unroll
        for (int c = 0; c < 2 * WGN; c++) {
            const int r = sm8 + c * 32;
            cp16(dbB + (uint32_t)(r * 32 + w4) * 4, Bk + (long)r * ldb);
        }
        asm volatile("cp.async.commit_group;" ::: "memory");
    };

    stage_copy(0, 0);
    stage_copy(1, 1);

    int cbuf = 0;
#pragma unroll 1
    for (int it = 0; it < NIT; it++) {
        asm volatile("cp.async.wait_group %0;" :: "n"(NSTAGE - 2) : "memory");
        __syncthreads();
        if (it + 2 < NIT) {
            int nb = cbuf + 2; if (nb >= NSTAGE) nb -= NSTAGE;
            stage_copy(it + 2, nb);
        }

        const uint32_t* sA = smem + cbuf * BUF_WORDS;
        const uint32_t* sB = sA + AWORDS;

        // MODE 2: write normalized fp32 attn back (each element staged once)
        if (MODE == 2) {
#pragma unroll
            for (int c = 0; c < 2 * WGM; c++) {
                const int m = sm8 + c * 32;
                const uint4 d = *reinterpret_cast<const uint4*>(sA + m * 32 + w4);
                const float iv = invs[c];
                float2 f0 = __half22float2(*reinterpret_cast<const __half2*>(&d.x));
                float2 f1 = __half22float2(*reinterpret_cast<const __half2*>(&d.y));
                float2 f2 = __half22float2(*reinterpret_cast<const __half2*>(&d.z));
                float2 f3 = __half22float2(*reinterpret_cast<const __half2*>(&d.w));
                float4 o0 = make_float4(f0.x * iv, f0.y * iv, f1.x * iv, f1.y * iv);
                float4 o1 = make_float4(f2.x * iv, f2.y * iv, f3.x * iv, f3.y * iv);
                float* dst = aux + (bm + m) * (long)lda + it * 64 + skc * 8;
                *reinterpret_cast<float4*>(dst)     = o0;
                *reinterpret_cast<float4*>(dst + 4) = o1;
            }
        }

        // fragment loader for k16 step ks (0..3); all rows ≡ grp (mod 8)
        auto load_frags = [&](int ks, uint32_t af[4][4], uint32_t bf[8][2]) {
            const int sw0 = ((2 * ks)     ^ grp) * 4 + tg;
            const int sw1 = ((2 * ks + 1) ^ grp) * 4 + tg;
#pragma unroll
            for (int mt = 0; mt < 4; mt++) {
                const int r0 = (wm + mt * 16 + grp) * 32;
                const int r1 = r0 + 8 * 32;
                af[mt][0] = sA[r0 + sw0];
                af[mt][1] = sA[r1 + sw0];
                af[mt][2] = sA[r0 + sw1];
                af[mt][3] = sA[r1 + sw1];
            }
#pragma unroll
            for (int nt = 0; nt < 8; nt++) {
                const int rb = (wn + nt * 8 + grp) * 32;
                bf[nt][0] = sB[rb + sw0];
                bf[nt][1] = sB[rb + sw1];
            }
        };

        uint32_t af[2][4][4], bf[2][8][2];
        load_frags(0, af[0], bf[0]);
#pragma unroll
        for (int ks = 0; ks < 4; ks++) {
            const int cur = ks & 1;
            if (ks < 3) load_frags(ks + 1, af[cur ^ 1], bf[cur ^ 1]);
#pragma unroll
            for (int mt = 0; mt < 4; mt++)
#pragma unroll
                for (int nt = 0; nt < 8; nt++)
                    mma_f16(acc[mt][nt][0], acc[mt][nt][1], acc[mt][nt][2], acc[mt][nt][3],
                            af[cur][mt][0], af[cur][mt][1], af[cur][mt][2], af[cur][mt][3],
                            bf[cur][nt][0], bf[cur][nt][1]);
        }
        cbuf++; if (cbuf >= NSTAGE) cbuf = 0;
    }

    // ---- epilogue ----
    if (MODE == 1) {
        __half* Ch = (__half*)Cv;
        const int ct = (int)((bn + wn) >> 6);
#pragma unroll
        for (int mt = 0; mt < 4; mt++) {
            const long r0 = bm + wm + mt * 16 + grp;
            float rs0 = 0.0f, rs1 = 0.0f;
#pragma unroll
            for (int nt = 0; nt < 8; nt++) {
                const int cn = (int)bn + wn + nt * 8 + 2 * tg;
                const float e00 = __expf(acc[mt][nt][0] * alpha);
                const float e01 = __expf(acc[mt][nt][1] * alpha);
                const float e10 = __expf(acc[mt][nt][2] * alpha);
                const float e11 = __expf(acc[mt][nt][3] * alpha);
                const __half2 h0 = __floats2half2_rn(e00, e01);
                const __half2 h1 = __floats2half2_rn(e10, e11);
                const float2 b0 = __half22float2(h0);
                const float2 b1 = __half22float2(h1);
                rs0 += b0.x + b0.y;
                rs1 += b1.x + b1.y;
                *reinterpret_cast<__half2*>(Ch + r0 * (long)ldc + cn)       = h0;
                *reinterpret_cast<__half2*>(Ch + (r0 + 8) * (long)ldc + cn) = h1;
            }
            rs0 += __shfl_xor_sync(0xffffffffu, rs0, 1);
            rs0 += __shfl_xor_sync(0xffffffffu, rs0, 2);
            rs1 += __shfl_xor_sync(0xffffffffu, rs1, 1);
            rs1 += __shfl_xor_sync(0xffffffffu, rs1, 2);
            if (tg == 0) {
                aux[(size_t)r0 * 64 + ct]       = rs0;
                aux[(size_t)(r0 + 8) * 64 + ct] = rs1;
            }
        }
    } else if (MODE == 3) {
        __half* Ch = (__half*)Cv;
#pragma unroll
        for (int mt = 0; mt < 4; mt++) {
            const long r0 = bm + wm + mt * 16 + grp;
#pragma unroll
            for (int nt = 0; nt < 8; nt++) {
                const int cn = (int)bn + wn + nt * 8 + 2 * tg;
                float v00 = acc[mt][nt][0] * alpha;
                float v01 = acc[mt][nt][1] * alpha;
                float v10 = acc[mt][nt][2] * alpha;
                float v11 = acc[mt][nt][3] * alpha;
                if (HASBIAS) {
                    const float b0 = bias[cn], b1 = bias[cn + 1];
                    v00 += b0; v01 += b1;
                    v10 += b0; v11 += b1;
                }
                Ch[(size_t)cn * ldc + r0]           = __float2half_rn(v00);
                Ch[(size_t)(cn + 1) * ldc + r0]     = __float2half_rn(v01);
                Ch[(size_t)cn * ldc + r0 + 8]       = __float2half_rn(v10);
                Ch[(size_t)(cn + 1) * ldc + r0 + 8] = __float2half_rn(v11);
            }
        }
    } else {
#pragma unroll
        for (int mt = 0; mt < 4; mt++) {
            const long r0 = bm + wm + mt * 16 + grp;
            float s0 = 1.0f, s1 = 1.0f;
            if (MODE == 2) { s0 = invrow[r0]; s1 = invrow[r0 + 8]; }
#pragma unroll
            for (int nt = 0; nt < 8; nt++) {
                const int cn = (int)bn + wn + nt * 8 + 2 * tg;
                float v00 = acc[mt][nt][0] * alpha * s0;
                float v01 = acc[mt][nt][1] * alpha * s0;
                float v10 = acc[mt][nt][2] * alpha * s1;
                float v11 = acc[mt][nt][3] * alpha * s1;
                if (HASBIAS) {
                    const float b0 = bias[cn], b1 = bias[cn + 1];
                    v00 += b0; v01 += b1;
                    v10 += b0; v11 += b1;
                }
                if (OUTHALF) {
                    __half* Ch = (__half*)Cv;
                    *reinterpret_cast<__half2*>(Ch + r0 * (long)ldc + cn)       = __floats2half2_rn(v00, v01);
                    *reinterpret_cast<__half2*>(Ch + (r0 + 8) * (long)ldc + cn) = __floats2half2_rn(v10, v11);
                } else {
                    float* Cf = (float*)Cv;
                    *reinterpret_cast<float2*>(Cf + r0 * (long)ldc + cn)       = make_float2(v00, v01);
                    *reinterpret_cast<float2*>(Cf + (r0 + 8) * (long)ldc + cn) = make_float2(v10, v11);
                }
            }
        }
    }
}

// ---------------------------------------------------------------------------
__global__ void __launch_bounds__(256) f2h_kernel(const float* __restrict__ q,
                                                  const float* __restrict__ k,
                                                  const float* __restrict__ v)
{
    const int z = blockIdx.y;
    const float* src = z == 0 ? q : z == 1 ? k : v;
    __half* dst = z == 0 ? g_qin : z == 1 ? g_kin : g_vin;
    const size_t i = (size_t)blockIdx.x * 256 + threadIdx.x;
    const float4 val = reinterpret_cast<const float4*>(src)[i];
    __half2 h0 = __floats2half2_rn(val.x, val.y);
    __half2 h1 = __floats2half2_rn(val.z, val.w);
    uint2 o;
    o.x = *reinterpret_cast<uint32_t*>(&h0);
    o.y = *reinterpret_cast<uint32_t*>(&h1);
    reinterpret_cast<uint2*>(dst)[i] = o;
}

// merged weight transpose: z 0..11 -> Wq/Wk/Wv heads (8 x-blocks), z=12 -> Wo
__global__ void __launch_bounds__(256) transw_kernel(
    const float* __restrict__ Wq, const float* __restrict__ Wk,
    const float* __restrict__ Wv, const float* __restrict__ Wo)
{
    __shared__ float t[32][33];
    const int z = blockIdx.z;
    const float* src;
    __half* dst;
    int R, C;
    if (z == 12) { src = Wo; dst = g_WoTh; R = DM; C = DM; }
    else {
        const int mat = z >> 2, head = z & 3;
        const float* W = mat == 0 ? Wq : mat == 1 ? Wk : Wv;
        src = W + (size_t)head * DM * DK;
        dst = g_WTh + (size_t)z * DK * DM;
        R = DM; C = DK;
        if (blockIdx.x >= 8) return;
    }

    const int c0 = blockIdx.x * 32, r0 = blockIdx.y * 32;
    const int tx = threadIdx.x & 31, ty = threadIdx.x >> 5;
#pragma unroll
    for (int i = 0; i < 4; i++)
        t[ty + i * 8][tx] = src[(size_t)(r0 + ty + i * 8) * C + c0 + tx];
    __syncthreads();
#pragma unroll
    for (int i = 0; i < 4; i++)
        dst[(size_t)(c0 + ty + i * 8) * R + r0 + tx] = __float2half_rn(t[tx][ty + i * 8]);
}

__global__ void __launch_bounds__(256) invsum_kernel()
{
    const int row  = blockIdx.x * 8 + (threadIdx.x >> 5);
    const int lane = threadIdx.x & 31;
    float s = g_psum[(size_t)row * 64 + lane] + g_psum[(size_t)row * 64 + 32 + lane];
#pragma unroll
    for (int o = 16; o > 0; o >>= 1) s += __shfl_xor_sync(0xffffffffu, s, o);
    if (lane == 0) g_invsum[row] = 1.0f / s;
}

// ---------------------------------------------------------------------------
// proj: z 0..3 Q heads, 4..7 K heads, 8..11 V heads (V written transposed)
// ---------------------------------------------------------------------------
__global__ void __launch_bounds__(256, 1) proj_tc(
    const float* __restrict__ bq, const float* __restrict__ bk, const float* __restrict__ bv)
{
    const int z = blockIdx.z, mat = z >> 2, head = z & 3;
    const __half* A    = mat == 0 ? g_qin : mat == 1 ? g_kin : g_vin;
    const __half* B    = g_WTh + (size_t)z * DK * DM;
    const float*  bias = (mat == 0 ? bq : mat == 1 ? bk : bv) + head * DK;
    if (mat == 2) {
        __half* C = g_VTh + (size_t)head * BS_TOT * DK;
        const long b = (long)blockIdx.y / 32;
        __half* Cb = C + b * SEQ * DK - b * SEQ;
        gemm_h<2, 4, true, true, 3>(A, DM, B, DM, Cb, SEQ, DM, 1.0f, bias, nullptr, nullptr);
    } else {
        __half* C = (mat == 0 ? g_Qh : g_Kh) + (size_t)head * BS_TOT * DK;
        gemm_h<2, 4, true, true, 0>(A, DM, B, DM, C, DK, DM, 1.0f, bias, nullptr, nullptr);
    }
}

__global__ void __launch_bounds__(256, 1) scores_tc()
{
    const int z = blockIdx.z;
    gemm_h<4, 2, false, true, 1>(g_Qh + (size_t)z * SEQ * DK, DK,
                                 g_Kh + (size_t)z * SEQ * DK, DK,
                                 g_Eh + (size_t)z * SEQ * SEQ, SEQ, DK, 0.0625f,
                                 nullptr, g_psum + (size_t)z * SEQ * 64, nullptr);
}

__global__ void __launch_bounds__(256, 1) av_tc(float* __restrict__ attn_out)
{
    float* attn = attn_out ? attn_out : g_attn_fallback;
    const int z = blockIdx.z, h = z >> 1, b = z & 1;
    gemm_h<2, 4, false, true, 2>(g_Eh + (size_t)z * SEQ * SEQ, SEQ,
                                 g_VTh + (size_t)z * DK * SEQ, SEQ,
                                 g_HOh + (size_t)b * SEQ * DM + h * DK, DM, SEQ, 1.0f,
                                 nullptr,
                                 attn + (size_t)z * SEQ * SEQ,
                                 g_invsum + (size_t)z * SEQ);
}

__global__ void __launch_bounds__(256, 1) outproj_tc(const float* __restrict__ bo,
                                                     float* __restrict__ out)
{
    gemm_h<2, 4, true, false, 0>(g_HOh, DM, g_WoTh, DM, out, DM, DM, 1.0f, bo,
                                 nullptr, nullptr);
}

// ---------------------------------------------------------------------------
extern "C" void kernel_launch(void* const* d_in, const int* in_sizes, int n_in,
                              void* d_out, int out_size)
{
    const float* q  = (const float*)d_in[0];
    const float* k  = (const float*)d_in[1];
    const float* v  = (const float*)d_in[2];
    const float* Wq = (const float*)d_in[3];
    const float* bq = (const float*)d_in[4];
    const float* Wk = (const float*)d_in[5];
    const float* bk = (const float*)d_in[6];
    const float* Wv = (const float*)d_in[7];
    const float* bv = (const float*)d_in[8];
    const float* Wo = (const float*)d_in[9];
    const float* bo = (const float*)d_in[10];

    float* out = (float*)d_out;
    const long OUT_ELEMS  = (long)NB * SEQ * DM;
    const long ATTN_ELEMS = (long)NH * NB * SEQ * SEQ;
    float* attn_out = nullptr;
    if ((long)out_size >= OUT_ELEMS + ATTN_ELEMS) attn_out = out + OUT_ELEMS;

    cudaFuncSetAttribute(proj_tc,    cudaFuncAttributeMaxDynamicSharedMemorySize, SMEM_BYTES);
    cudaFuncSetAttribute(scores_tc,  cudaFuncAttributeMaxDynamicSharedMemorySize, SMEM_BYTES);
    cudaFuncSetAttribute(av_tc,      cudaFuncAttributeMaxDynamicSharedMemorySize, SMEM_BYTES);
    cudaFuncSetAttribute(outproj_tc, cudaFuncAttributeMaxDynamicSharedMemorySize, SMEM_BYTES);

    f2h_kernel<<<dim3(BS_TOT * DM / 4 / 256, 3), 256>>>(q, k, v);

    transw_kernel<<<dim3(32, 32, 13), 256>>>(Wq, Wk, Wv, Wo);

    // proj (Q, K normal; V transposed directly into g_VTh)
    proj_tc<<<dim3(1, 64, 12), 256, SMEM_BYTES>>>(bq, bk, bv);

    // scores: exp(QK^T/16) fp16 + row partial sums
    scores_tc<<<dim3(32, 16, 8), 256, SMEM_BYTES>>>();

    invsum_kernel<<<dim3(NROWS / 8), 256>>>();

    // av: normalized attn (fp32 to d_out) + HO
    av_tc<<<dim3(1, 32, 8), 256, SMEM_BYTES>>>(attn_out);

    outproj_tc<<<dim3(4, 64, 1), 256, SMEM_BYTES>>>(bo, out);
}